// round 9
// baseline (speedup 1.0000x reference)
#include <cuda_runtime.h>
#include <cuda_fp16.h>
#include <cstdint>

// Deformable conv2d B=8, Cin=Cout=128, H=W=64, 3x3 s1 p1 DG=1.
// f16 HMMA (fp32 accum), warp-specialized: 8 MMA warps + 4 gather warps.
// One CTA per (b, ho-pair): 256 CTAs, N=128, 2 CTAs/SM, 24 warps/SM.

#define THREADS 384
static constexpr int KTOT = 1152;
static constexpr int NSTEP = 48;        // 16 cg8 x 3 tb (K=24 per step)

static constexpr int XROWS = 13;
static constexpr int XST2  = 68;            // X row stride (u32 slots)
static constexpr int XCH2  = XROWS * XST2;  // 884
static constexpr int XWIN2 = 8 * XCH2;      // 7072 u32 per buffer
static constexpr int BST2  = 136;           // B row stride (u32)
static constexpr int BBUF  = 12 * BST2;     // 1632 u32 per buffer
static constexpr int XF4   = 8 * XROWS * 16;  // 1664 float4 per window

// smem layout (bytes)
static constexpr int OFF_MI = 0;            // int[1152]     4608
static constexpr int OFF_MW = 4608;         // float4[1152] 18432
static constexpr int OFF_X  = 23040;        // 2 x 7072 u32 56576
static constexpr int OFF_B  = 79616;        // 2 x 1632 u32 13056
static constexpr int SMEM_TOTAL = 92672;

// frag-ordered fp16 weights: [(slice*3+ks)*128 + co][tq], half2 = (ch even, ch odd)
__device__ uint32_t g_wtF[NSTEP * 3 * 128 * 4];

__device__ __forceinline__ void mma_f16(float* d, uint32_t a0, uint32_t a1,
                                        uint32_t b0) {
    asm volatile(
        "mma.sync.aligned.m16n8k8.row.col.f32.f16.f16.f32 "
        "{%0,%1,%2,%3}, {%4,%5}, {%6}, {%0,%1,%2,%3};"
        : "+f"(d[0]), "+f"(d[1]), "+f"(d[2]), "+f"(d[3])
        : "r"(a0), "r"(a1), "r"(b0));
}
__device__ __forceinline__ uint32_t h2u(__half2 h) { return *(uint32_t*)&h; }

__global__ void wt_permute(const float* __restrict__ w) {
    int idx = blockIdx.x * 256 + threadIdx.x;
    if (idx >= NSTEP * 3 * 128 * 4) return;
    int tq = idx & 3, co = (idx >> 2) & 127, rest = idx >> 9;
    int ks = rest % 3, slice = rest / 3;
    int cg8 = slice / 3, tb = slice % 3;
    int tap = tb * 3 + ks, ch0 = cg8 * 8 + 2 * tq;
    g_wtF[idx] = h2u(__floats2half2_rn(w[co * KTOT + ch0 * 9 + tap],
                                       w[co * KTOT + (ch0 + 1) * 9 + tap]));
}

// stage one float4 of an X window as interleaved half2 pairs PS[s]=(x[s-1],x[s])
// NOTE: caller must keep warps fully active (warp-aligned ranges) for the shfl.
__device__ __forceinline__ void stage_unit(uint32_t* xw, const float* xcb,
                                           int idx, int lo) {
    int ch = idx / (XROWS * 16), rr = idx - ch * (XROWS * 16);
    int r = rr >> 4, w4 = rr & 15;
    float4 f = *(const float4*)(xcb + ch * 4096 + (lo + r) * 64 + w4 * 4);
    float prev = __shfl_up_sync(0xffffffffu, f.w, 1);
    uint32_t* dst = xw + ch * XCH2 + r * XST2 + 4 * w4;
    *(uint4*)dst = make_uint4(h2u(__floats2half2_rn(prev, f.x)),
                              h2u(__floats2half2_rn(f.x, f.y)),
                              h2u(__floats2half2_rn(f.y, f.z)),
                              h2u(__floats2half2_rn(f.z, f.w)));
    if (w4 == 15) dst[4] = h2u(__floats2half2_rn(f.w, 0.f));
}

// gather one (tap, px) unit over 8 channels into the B tile
__device__ __forceinline__ void gather_unit(const uint32_t* xw, const float* xcb,
                                            uint32_t* bD, const int* sMI,
                                            const float4* sMW, int idx, int ptb,
                                            int lo) {
    const int px = idx & 127, ti = idx >> 7;
    int tap = (ptb * 3 + ti) * 128 + px;
    int mi = sMI[tap];
    float4 mw = sMW[tap];
    int cy0 = mi & 63, cy1 = (mi >> 6) & 63, sl = mi >> 12;
    int wr0 = cy0 - lo, wr1 = cy1 - lo;
    bool in0 = (unsigned)wr0 < (unsigned)XROWS;
    bool in1 = (unsigned)wr1 < (unsigned)XROWS;
    int wr0c = min(max(wr0, 0), XROWS - 1), wr1c = min(max(wr1, 0), XROWS - 1);
    const uint32_t* p0 = xw + wr0c * XST2 + sl;
    const uint32_t* p1 = xw + wr1c * XST2 + sl;
    uint32_t* bRow = bD + px;
    if (in0 && in1) {
        #pragma unroll
        for (int jj = 0; jj < 4; jj++) {
            float vv[2];
            #pragma unroll
            for (int h = 0; h < 2; h++) {
                int ch = 2 * jj + h;
                float2 t0 = __half22float2(*(const __half2*)&p0[ch * XCH2]);
                float2 t1 = __half22float2(*(const __half2*)&p1[ch * XCH2]);
                float v = mw.x * t0.x;
                v = fmaf(mw.y, t0.y, v);
                v = fmaf(mw.z, t1.x, v);
                vv[h] = fmaf(mw.w, t1.y, v);
            }
            bRow[(ti * 4 + jj) * BST2] = h2u(__floats2half2_rn(vv[0], vv[1]));
        }
    } else {  // rare: a sampled row falls outside the staged window
        int cx0 = min(max(sl - 1, 0), 63), cx1 = min(sl, 63);
        #pragma unroll
        for (int jj = 0; jj < 4; jj++) {
            float vv[2];
            #pragma unroll
            for (int h = 0; h < 2; h++) {
                int ch = 2 * jj + h;
                const float* xp = xcb + ch * 4096;
                float2 t0, t1;
                if (in0) t0 = __half22float2(*(const __half2*)&p0[ch * XCH2]);
                else     t0 = make_float2(xp[cy0 * 64 + cx0], xp[cy0 * 64 + cx1]);
                if (in1) t1 = __half22float2(*(const __half2*)&p1[ch * XCH2]);
                else     t1 = make_float2(xp[cy1 * 64 + cx0], xp[cy1 * 64 + cx1]);
                float v = mw.x * t0.x;
                v = fmaf(mw.y, t0.y, v);
                v = fmaf(mw.z, t1.x, v);
                vv[h] = fmaf(mw.w, t1.y, v);
            }
            bRow[(ti * 4 + jj) * BST2] = h2u(__floats2half2_rn(vv[0], vv[1]));
        }
    }
}

__global__ __launch_bounds__(THREADS, 2)
void deform_conv_ws(const float* __restrict__ x,
                    const float* __restrict__ offs,
                    float* __restrict__ out) {
    extern __shared__ char smem[];
    int*      sMI = (int*)(smem + OFF_MI);
    float4*   sMW = (float4*)(smem + OFF_MW);
    uint32_t* sX  = (uint32_t*)(smem + OFF_X);
    uint32_t* sBu = (uint32_t*)(smem + OFF_B);

    const int t = threadIdx.x, lane = t & 31, warp = t >> 5;
    const int b = blockIdx.x >> 5, ho2 = blockIdx.x & 31;
    const int lo = min(max(2 * ho2 - 5, 0), 64 - XROWS);
    const float* xg = x + b * 524288;

    // ---- tap metadata: 9 taps x 2 rows x 64 px (3 iters over 384 threads) ----
    const float* ob = offs + b * 18 * 4096;
    for (int i = t; i < 1152; i += THREADS) {
        int k = i >> 7, rp = i & 127, r = rp >> 6, p = rp & 63;
        int ho = 2 * ho2 + r;
        float dy = ob[(2 * k) * 4096 + ho * 64 + p];
        float dx = ob[(2 * k + 1) * 4096 + ho * 64 + p];
        float py = (float)(ho - 1 + k / 3) + dy;
        float px = (float)(p  - 1 + k % 3) + dx;
        float fy = floorf(py), fx = floorf(px);
        int y0 = (int)fy, x0 = (int)fx;
        float wy = py - fy, wx = px - fx;
        float wy1 = 1.f - wy, wx1 = 1.f - wx;
        float w00 = wy1 * wx1, w01 = wy1 * wx, w10 = wy * wx1, w11 = wy * wx;
        bool vy0 = (unsigned)y0       < 64u, vy1 = (unsigned)(y0 + 1) < 64u;
        bool vx0 = (unsigned)x0       < 64u, vx1 = (unsigned)(x0 + 1) < 64u;
        if (!(vy0 && vx0)) w00 = 0.f;
        if (!(vy0 && vx1)) w01 = 0.f;
        if (!(vy1 && vx0)) w10 = 0.f;
        if (!(vy1 && vx1)) w11 = 0.f;
        int cy0 = min(max(y0, 0), 63), cy1 = min(max(y0 + 1, 0), 63);
        int s   = min(max(x0, -1), 63) + 1;      // pair slot: PS[s]=(x[s-1],x[s])
        sMI[i] = cy0 | (cy1 << 6) | (s << 12);
        sMW[i] = make_float4(w00, w01, w10, w11);
    }

    // ---- prologue: window 0 (1664 f4) + chunk 0 of window 1 (576 f4) ----
    #pragma unroll
    for (int j = 0; j < 6; j++) {
        int idx = j * THREADS + t;           // boundaries 1664 & 2240 warp-aligned
        if (idx < 2240) {
            if (idx < XF4) stage_unit(sX, xg, idx, lo);
            else           stage_unit(sX + XWIN2, xg + 8 * 4096, idx - XF4, lo);
        }
    }
    __syncthreads();

    const int g = lane >> 2, tq = lane & 3;
    const int warpM = warp >> 1, warpN = warp & 1;   // consumers only
    float acc[2][8][4];
    #pragma unroll
    for (int m = 0; m < 2; m++)
        #pragma unroll
        for (int n = 0; n < 8; n++)
            #pragma unroll
            for (int c = 0; c < 4; c++) acc[m][n][c] = 0.f;

    // producers gather step 0
    if (warp >= 8) {
        int t2 = t - 256;
        gather_unit(sX, xg, sBu, sMI, sMW, t2,       0, lo);
        gather_unit(sX, xg, sBu, sMI, sMW, t2 + 128, 0, lo);
        gather_unit(sX, xg, sBu, sMI, sMW, t2 + 256, 0, lo);
    }

    // ---- main pipeline ----
    for (int s = 0; s < NSTEP; s++) {
        __syncthreads();   // B(s) ready; X window for gather(s+1) ready

        if (warp < 8) {
            // ---- consumers: MMA step s ----
            const uint32_t* bB = sBu + (s & 1) * BBUF + warpN * 64 + g;
            #pragma unroll
            for (int ks = 0; ks < 3; ks++) {
                const uint32_t* ap =
                    g_wtF + (((s * 3 + ks) * 128 + warpM * 32) << 2) + lane;
                uint32_t a00 = __ldg(ap);
                uint32_t a01 = __ldg(ap + 32);
                uint32_t a10 = __ldg(ap + 64);
                uint32_t a11 = __ldg(ap + 96);
                const uint32_t* bU = bB + (ks * 4 + tq) * BST2;
                #pragma unroll
                for (int nt = 0; nt < 8; nt++) {
                    uint32_t b0 = bU[nt * 8];
                    mma_f16(acc[0][nt], a00, a01, b0);
                    mma_f16(acc[1][nt], a10, a11, b0);
                }
            }
            // ---- consumers: stage chunk of window c = (s+4)/3 ----
            int c4 = s + 4, c = c4 / 3, ck = c4 - 3 * c;
            if (c < 16) {
                uint32_t* xwn = sX + (c & 1) * XWIN2;
                const float* xcb = xg + c * 8 * 4096;
                int base = ck * 576;                     // chunks: 576,576,512
                int end  = min(base + 576, XF4);
                #pragma unroll
                for (int j = 0; j < 3; j++) {
                    int idx = base + j * 256 + t;        // t < 256, warp-aligned
                    if (idx < end) stage_unit(xwn, xcb, idx, lo);
                }
            }
        } else if (s < NSTEP - 1) {
            // ---- producers: gather step s+1 ----
            const int sp = s + 1;
            const int pcg = sp / 3, ptb = sp - pcg * 3;
            const uint32_t* xw = sX + (pcg & 1) * XWIN2;
            const float* xcb = xg + pcg * 8 * 4096;
            uint32_t* bD = sBu + (sp & 1) * BBUF;
            int t2 = t - 256;
            gather_unit(xw, xcb, bD, sMI, sMW, t2,       ptb, lo);
            gather_unit(xw, xcb, bD, sMI, sMW, t2 + 128, ptb, lo);
            gather_unit(xw, xcb, bD, sMI, sMW, t2 + 256, ptb, lo);
        }
    }

    // ---- epilogue (consumers): D[m=cout][n] -> out row 2*ho2+warpN ----
    if (warp < 8) {
        float* o = out + b * 524288 + (2 * ho2 + warpN) * 64;
        #pragma unroll
        for (int mt = 0; mt < 2; mt++) {
            int row0 = warpM * 32 + mt * 16 + g;
            #pragma unroll
            for (int nt = 0; nt < 8; nt++) {
                int p = nt * 8 + 2 * tq;
                *(float2*)(o + row0 * 4096 + p) =
                    make_float2(acc[mt][nt][0], acc[mt][nt][1]);
                *(float2*)(o + (row0 + 8) * 4096 + p) =
                    make_float2(acc[mt][nt][2], acc[mt][nt][3]);
            }
        }
    }
}

extern "C" void kernel_launch(void* const* d_in, const int* in_sizes, int n_in,
                              void* d_out, int out_size) {
    const float* x    = (const float*)d_in[0];
    const float* offs = (const float*)d_in[1];
    const float* wgt  = (const float*)d_in[2];
    wt_permute<<<(NSTEP * 3 * 128 * 4 + 255) / 256, 256>>>(wgt);
    cudaFuncSetAttribute(deform_conv_ws,
                         cudaFuncAttributeMaxDynamicSharedMemorySize, SMEM_TOTAL);
    deform_conv_ws<<<256, THREADS, SMEM_TOTAL>>>(x, offs, (float*)d_out);
}

// round 10
// speedup vs baseline: 1.7124x; 1.7124x over previous
#include <cuda_runtime.h>
#include <cuda_fp16.h>
#include <cstdint>

// Deformable conv2d B=8, Cin=Cout=128, H=W=64, 3x3 s1 p1 DG=1.
// f16 HMMA m16n8k16 (fp32 accum), pair-interleaved fp16 X window,
// frag-ordered weight LDG. One CTA per (b, ho-pair): 256 CTAs, N=128.
// 16 steps of K=72 (one 8-channel group per step).

#define THREADS 256
static constexpr int KTOT = 1152;
static constexpr int NSTEP = 16;            // one cg8 per step, K=72

static constexpr int XROWS = 12;
static constexpr int XST2  = 68;            // X row stride (u32 slots)
static constexpr int XCH2  = XROWS * XST2;  // 816
static constexpr int XWIN2 = 8 * XCH2;      // 6528 u32 per buffer
static constexpr int XF4   = 8 * XROWS * 16;// 1536 float4 per window
static constexpr int BST2  = 136;           // B row stride (u32): 8tq+g banks
static constexpr int BBUF  = 36 * BST2;     // 4896 u32 per buffer

// smem layout (bytes)
static constexpr int OFF_MI = 0;            // int[1152]      4608
static constexpr int OFF_MW = 4608;         // float4[1152]  18432
static constexpr int OFF_X  = 23040;        // 2 x 26112 =   52224
static constexpr int OFF_B  = 75264;        // 2 x 19584 =   39168
static constexpr int SMEM_TOTAL = 114432;

// frag-ordered fp16 weights: [((cg8*9+tap)*128 + co)*4 + tq],
// half2 = (ch = cg8*8+2tq, ch+1) at kernel tap `tap`
__device__ uint32_t g_wtF[NSTEP * 9 * 128 * 4];

__device__ __forceinline__ void mma_k16(float* d, uint32_t a0, uint32_t a1,
                                        uint32_t a2, uint32_t a3,
                                        uint32_t b0, uint32_t b1) {
    asm volatile(
        "mma.sync.aligned.m16n8k16.row.col.f32.f16.f16.f32 "
        "{%0,%1,%2,%3}, {%4,%5,%6,%7}, {%8,%9}, {%0,%1,%2,%3};"
        : "+f"(d[0]), "+f"(d[1]), "+f"(d[2]), "+f"(d[3])
        : "r"(a0), "r"(a1), "r"(a2), "r"(a3), "r"(b0), "r"(b1));
}
__device__ __forceinline__ void mma_k8(float* d, uint32_t a0, uint32_t a1,
                                       uint32_t b0) {
    asm volatile(
        "mma.sync.aligned.m16n8k8.row.col.f32.f16.f16.f32 "
        "{%0,%1,%2,%3}, {%4,%5}, {%6}, {%0,%1,%2,%3};"
        : "+f"(d[0]), "+f"(d[1]), "+f"(d[2]), "+f"(d[3])
        : "r"(a0), "r"(a1), "r"(b0));
}
__device__ __forceinline__ uint32_t h2u(__half2 h) { return *(uint32_t*)&h; }

__global__ void wt_permute(const float* __restrict__ w) {
    int idx = blockIdx.x * 256 + threadIdx.x;
    if (idx >= NSTEP * 9 * 128 * 4) return;
    int tq = idx & 3, co = (idx >> 2) & 127, rest = idx >> 9;
    int tap = rest % 9, cg8 = rest / 9;
    int ch0 = cg8 * 8 + 2 * tq;
    g_wtF[idx] = h2u(__floats2half2_rn(w[co * KTOT + ch0 * 9 + tap],
                                       w[co * KTOT + (ch0 + 1) * 9 + tap]));
}

// stage one float4 of an X window as interleaved half2 pairs PS[s]=(x[s-1],x[s])
// caller must keep warps fully active (warp-aligned ranges) for the shfl.
__device__ __forceinline__ void stage_unit(uint32_t* xw, const float* xcb,
                                           int idx, int lo) {
    int ch = idx / (XROWS * 16), rr = idx - ch * (XROWS * 16);
    int r = rr >> 4, w4 = rr & 15;
    float4 f = *(const float4*)(xcb + ch * 4096 + (lo + r) * 64 + w4 * 4);
    float prev = __shfl_up_sync(0xffffffffu, f.w, 1);
    uint32_t* dst = xw + ch * XCH2 + r * XST2 + 4 * w4;
    *(uint4*)dst = make_uint4(h2u(__floats2half2_rn(prev, f.x)),
                              h2u(__floats2half2_rn(f.x, f.y)),
                              h2u(__floats2half2_rn(f.y, f.z)),
                              h2u(__floats2half2_rn(f.z, f.w)));
    if (w4 == 15) dst[4] = h2u(__floats2half2_rn(f.w, 0.f));
}

// gather one (tap, px) unit over 8 channels into the B tile
// idx in [0, 1152): tap = idx>>7, px = idx&127; B rows tap*4 + jj.
__device__ __forceinline__ void gather_unit(const uint32_t* xw, const float* xcb,
                                            uint32_t* bD, const int* sMI,
                                            const float4* sMW, int idx, int lo) {
    const int px = idx & 127, tap = idx >> 7;
    int mi = sMI[tap * 128 + px];
    float4 mw = sMW[tap * 128 + px];
    int cy0 = mi & 63, cy1 = (mi >> 6) & 63, sl = mi >> 12;
    int wr0 = cy0 - lo, wr1 = cy1 - lo;
    bool in0 = (unsigned)wr0 < (unsigned)XROWS;
    bool in1 = (unsigned)wr1 < (unsigned)XROWS;
    int wr0c = min(max(wr0, 0), XROWS - 1), wr1c = min(max(wr1, 0), XROWS - 1);
    const uint32_t* p0 = xw + wr0c * XST2 + sl;
    const uint32_t* p1 = xw + wr1c * XST2 + sl;
    uint32_t* bRow = bD + px;
    if (in0 && in1) {
        #pragma unroll
        for (int jj = 0; jj < 4; jj++) {
            float vv[2];
            #pragma unroll
            for (int h = 0; h < 2; h++) {
                int ch = 2 * jj + h;
                float2 t0 = __half22float2(*(const __half2*)&p0[ch * XCH2]);
                float2 t1 = __half22float2(*(const __half2*)&p1[ch * XCH2]);
                float v = mw.x * t0.x;
                v = fmaf(mw.y, t0.y, v);
                v = fmaf(mw.z, t1.x, v);
                vv[h] = fmaf(mw.w, t1.y, v);
            }
            bRow[(tap * 4 + jj) * BST2] = h2u(__floats2half2_rn(vv[0], vv[1]));
        }
    } else {  // rare: a sampled row falls outside the staged window
        int cx0 = min(max(sl - 1, 0), 63), cx1 = min(sl, 63);
        #pragma unroll
        for (int jj = 0; jj < 4; jj++) {
            float vv[2];
            #pragma unroll
            for (int h = 0; h < 2; h++) {
                int ch = 2 * jj + h;
                const float* xp = xcb + ch * 4096;
                float2 t0, t1;
                if (in0) t0 = __half22float2(*(const __half2*)&p0[ch * XCH2]);
                else     t0 = make_float2(xp[cy0 * 64 + cx0], xp[cy0 * 64 + cx1]);
                if (in1) t1 = __half22float2(*(const __half2*)&p1[ch * XCH2]);
                else     t1 = make_float2(xp[cy1 * 64 + cx0], xp[cy1 * 64 + cx1]);
                float v = mw.x * t0.x;
                v = fmaf(mw.y, t0.y, v);
                v = fmaf(mw.z, t1.x, v);
                vv[h] = fmaf(mw.w, t1.y, v);
            }
            bRow[(tap * 4 + jj) * BST2] = h2u(__floats2half2_rn(vv[0], vv[1]));
        }
    }
}

__global__ __launch_bounds__(THREADS, 2)
void deform_conv_k72(const float* __restrict__ x,
                     const float* __restrict__ offs,
                     float* __restrict__ out) {
    extern __shared__ char smem[];
    int*      sMI = (int*)(smem + OFF_MI);
    float4*   sMW = (float4*)(smem + OFF_MW);
    uint32_t* sX  = (uint32_t*)(smem + OFF_X);
    uint32_t* sBu = (uint32_t*)(smem + OFF_B);

    const int t = threadIdx.x, lane = t & 31, warp = t >> 5;
    const int b = blockIdx.x >> 5, ho2 = blockIdx.x & 31;
    const int lo = min(max(2 * ho2 - 4, 0), 64 - XROWS);
    const float* xg = x + b * 524288;

    // ---- tap metadata: 9 taps x 2 rows x 64 px ----
    const float* ob = offs + b * 18 * 4096;
    for (int i = t; i < 1152; i += THREADS) {
        int k = i >> 7, rp = i & 127, r = rp >> 6, p = rp & 63;
        int ho = 2 * ho2 + r;
        float dy = ob[(2 * k) * 4096 + ho * 64 + p];
        float dx = ob[(2 * k + 1) * 4096 + ho * 64 + p];
        float py = (float)(ho - 1 + k / 3) + dy;
        float px = (float)(p  - 1 + k % 3) + dx;
        float fy = floorf(py), fx = floorf(px);
        int y0 = (int)fy, x0 = (int)fx;
        float wy = py - fy, wx = px - fx;
        float wy1 = 1.f - wy, wx1 = 1.f - wx;
        float w00 = wy1 * wx1, w01 = wy1 * wx, w10 = wy * wx1, w11 = wy * wx;
        bool vy0 = (unsigned)y0       < 64u, vy1 = (unsigned)(y0 + 1) < 64u;
        bool vx0 = (unsigned)x0       < 64u, vx1 = (unsigned)(x0 + 1) < 64u;
        if (!(vy0 && vx0)) w00 = 0.f;
        if (!(vy0 && vx1)) w01 = 0.f;
        if (!(vy1 && vx0)) w10 = 0.f;
        if (!(vy1 && vx1)) w11 = 0.f;
        int cy0 = min(max(y0, 0), 63), cy1 = min(max(y0 + 1, 0), 63);
        int s   = min(max(x0, -1), 63) + 1;      // pair slot: PS[s]=(x[s-1],x[s])
        sMI[i] = cy0 | (cy1 << 6) | (s << 12);
        sMW[i] = make_float4(w00, w01, w10, w11);
    }

    // ---- prologue: stage windows 0 and 1 (3072 f4) ----
    #pragma unroll
    for (int j = 0; j < 12; j++) {
        int idx = j * THREADS + t;
        if (idx < XF4) stage_unit(sX, xg, idx, lo);
        else           stage_unit(sX + XWIN2, xg + 8 * 4096, idx - XF4, lo);
    }
    __syncthreads();

    const int g = lane >> 2, tq = lane & 3;
    const int warpM = warp >> 1, warpN = warp & 1;
    float acc[2][8][4];
    #pragma unroll
    for (int m = 0; m < 2; m++)
        #pragma unroll
        for (int n = 0; n < 8; n++)
            #pragma unroll
            for (int c = 0; c < 4; c++) acc[m][n][c] = 0.f;

    // gather step 0 (warps 0-5, 6 units each; reads window 0, buffer 0)
    if (warp < 6) {
        #pragma unroll
        for (int u = 0; u < 6; u++)
            gather_unit(sX, xg, sBu, sMI, sMW, u * 192 + t, lo);
    }

    // ---- main pipeline: 16 steps, one cg8 each ----
    for (int s = 0; s < NSTEP; s++) {
        __syncthreads();   // B(s) ready; X window s+1 ready

        // ---- MMA step s: 4 x k16 (tap pairs) + 1 x k8 (tap 8) ----
        {
            const uint32_t* bB = sBu + (s & 1) * BBUF + warpN * 64 + g;
            const uint32_t* aBase = g_wtF + ((s * 9) * 128 + warpM * 32) * 4 + lane;
            #pragma unroll
            for (int j = 0; j < 4; j++) {
                const uint32_t* ap  = aBase + (2 * j) * 512;
                const uint32_t* ap2 = ap + 512;
                uint32_t a00 = __ldg(ap),        a01 = __ldg(ap + 32);
                uint32_t a02 = __ldg(ap2),       a03 = __ldg(ap2 + 32);
                uint32_t a10 = __ldg(ap + 64),   a11 = __ldg(ap + 96);
                uint32_t a12 = __ldg(ap2 + 64),  a13 = __ldg(ap2 + 96);
                const uint32_t* b0p = bB + (8 * j + tq) * BST2;
                const uint32_t* b1p = bB + (8 * j + 4 + tq) * BST2;
                #pragma unroll
                for (int nt = 0; nt < 8; nt++) {
                    uint32_t b0 = b0p[nt * 8];
                    uint32_t b1 = b1p[nt * 8];
                    mma_k16(acc[0][nt], a00, a01, a02, a03, b0, b1);
                    mma_k16(acc[1][nt], a10, a11, a12, a13, b0, b1);
                }
            }
            {   // tap 8 tail (k8)
                const uint32_t* ap = aBase + 8 * 512;
                uint32_t a00 = __ldg(ap),      a01 = __ldg(ap + 32);
                uint32_t a10 = __ldg(ap + 64), a11 = __ldg(ap + 96);
                const uint32_t* bU = bB + (32 + tq) * BST2;
                #pragma unroll
                for (int nt = 0; nt < 8; nt++) {
                    uint32_t b0 = bU[nt * 8];
                    mma_k8(acc[0][nt], a00, a01, b0);
                    mma_k8(acc[1][nt], a10, a11, b0);
                }
            }
        }

        if (s == NSTEP - 1) break;

        if (warp < 6) {
            // gather step s+1 from X window s+1 (buffer (s+1)&1)
            const uint32_t* xw = sX + ((s + 1) & 1) * XWIN2;
            const float* xcb = xg + (s + 1) * 8 * 4096;
            uint32_t* bD = sBu + ((s + 1) & 1) * BBUF;
            #pragma unroll
            for (int u = 0; u < 6; u++)
                gather_unit(xw, xcb, bD, sMI, sMW, u * 192 + t, lo);
        } else if (s + 2 < NSTEP) {
            // stage X window s+2 into buffer s&1 (window s is dead)
            uint32_t* xwn = sX + (s & 1) * XWIN2;
            const float* xcb = xg + (s + 2) * 8 * 4096;
            int t2 = t - 192;
            #pragma unroll
            for (int j = 0; j < 24; j++)
                stage_unit(xwn, xcb, j * 64 + t2, lo);
        }
    }

    // ---- epilogue: D[m=cout][n] -> out row 2*ho2+warpN ----
    float* o = out + b * 524288 + (2 * ho2 + warpN) * 64;
    #pragma unroll
    for (int mt = 0; mt < 2; mt++) {
        int row0 = warpM * 32 + mt * 16 + g;
        #pragma unroll
        for (int nt = 0; nt < 8; nt++) {
            int p = nt * 8 + 2 * tq;
            *(float2*)(o + row0 * 4096 + p) =
                make_float2(acc[mt][nt][0], acc[mt][nt][1]);
            *(float2*)(o + (row0 + 8) * 4096 + p) =
                make_float2(acc[mt][nt][2], acc[mt][nt][3]);
        }
    }
}

extern "C" void kernel_launch(void* const* d_in, const int* in_sizes, int n_in,
                              void* d_out, int out_size) {
    const float* x    = (const float*)d_in[0];
    const float* offs = (const float*)d_in[1];
    const float* wgt  = (const float*)d_in[2];
    wt_permute<<<(NSTEP * 9 * 128 * 4 + 255) / 256, 256>>>(wgt);
    cudaFuncSetAttribute(deform_conv_k72,
                         cudaFuncAttributeMaxDynamicSharedMemorySize, SMEM_TOTAL);
    deform_conv_k72<<<256, THREADS, SMEM_TOTAL>>>(x, offs, (float*)d_out);
}

// round 11
// speedup vs baseline: 1.9699x; 1.1504x over previous
#include <cuda_runtime.h>
#include <cuda_fp16.h>
#include <cstdint>

// Deformable conv2d B=8, Cin=Cout=128, H=W=64, 3x3 s1 p1 DG=1.
// f16 HMMA m16n8k16 (fp32 accum). Channel-packed fp16 X window:
// one LDS.128 = 8 channels at one (row,x) -> 4 LDS per bilinear gather unit.
// One CTA per (b, ho-pair): 256 CTAs, N=128, 16 steps of K=72.

#define THREADS 256
static constexpr int KTOT = 1152;
static constexpr int NSTEP = 16;            // one cg8 per step, K=72

static constexpr int XROWS = 13;
static constexpr int XWIN4 = XROWS * 64;    // uint4 per window buffer = 832
static constexpr int BST2  = 136;           // B row stride (u32)
static constexpr int BBUF  = 36 * BST2;     // 4896 u32 per buffer

// smem layout (bytes)
static constexpr int OFF_MI = 0;            // int[1152]      4608
static constexpr int OFF_MW = 4608;         // float4[1152]  18432
static constexpr int OFF_X  = 23040;        // 2 x 13312 =   26624
static constexpr int OFF_B  = 49664;        // 2 x 19584 =   39168
static constexpr int SMEM_TOTAL = 88832;

#define SWZ(x) ((x) ^ (((x) >> 3) & 7))

// frag-ordered fp16 weights: [((cg8*9+tap)*128 + co)*4 + tq]
__device__ uint32_t g_wtF[NSTEP * 9 * 128 * 4];

__device__ __forceinline__ void mma_k16(float* d, uint32_t a0, uint32_t a1,
                                        uint32_t a2, uint32_t a3,
                                        uint32_t b0, uint32_t b1) {
    asm volatile(
        "mma.sync.aligned.m16n8k16.row.col.f32.f16.f16.f32 "
        "{%0,%1,%2,%3}, {%4,%5,%6,%7}, {%8,%9}, {%0,%1,%2,%3};"
        : "+f"(d[0]), "+f"(d[1]), "+f"(d[2]), "+f"(d[3])
        : "r"(a0), "r"(a1), "r"(a2), "r"(a3), "r"(b0), "r"(b1));
}
__device__ __forceinline__ void mma_k8(float* d, uint32_t a0, uint32_t a1,
                                       uint32_t b0) {
    asm volatile(
        "mma.sync.aligned.m16n8k8.row.col.f32.f16.f16.f32 "
        "{%0,%1,%2,%3}, {%4,%5}, {%6}, {%0,%1,%2,%3};"
        : "+f"(d[0]), "+f"(d[1]), "+f"(d[2]), "+f"(d[3])
        : "r"(a0), "r"(a1), "r"(b0));
}
__device__ __forceinline__ uint32_t h2u(__half2 h) { return *(uint32_t*)&h; }

__global__ void wt_permute(const float* __restrict__ w) {
    int idx = blockIdx.x * 256 + threadIdx.x;
    if (idx >= NSTEP * 9 * 128 * 4) return;
    int tq = idx & 3, co = (idx >> 2) & 127, rest = idx >> 9;
    int tap = rest % 9, cg8 = rest / 9;
    int ch0 = cg8 * 8 + 2 * tq;
    g_wtF[idx] = h2u(__floats2half2_rn(w[co * KTOT + ch0 * 9 + tap],
                                       w[co * KTOT + (ch0 + 1) * 9 + tap]));
}

// stage one (row, x-quad) of a window: 8 coalesced LDG.128 + 4 swizzled STS.128
__device__ __forceinline__ void stage_unit(uint4* xw4, const float* xcb,
                                           int u, int lo) {
    int r = u >> 4, q = u & 15;
    const float* src = xcb + (lo + r) * 64 + 4 * q;
    uint32_t h[4][4];
    #pragma unroll
    for (int p = 0; p < 4; p++) {
        float4 a = *(const float4*)(src + (2 * p) * 4096);
        float4 b = *(const float4*)(src + (2 * p + 1) * 4096);
        h[0][p] = h2u(__floats2half2_rn(a.x, b.x));
        h[1][p] = h2u(__floats2half2_rn(a.y, b.y));
        h[2][p] = h2u(__floats2half2_rn(a.z, b.z));
        h[3][p] = h2u(__floats2half2_rn(a.w, b.w));
    }
    #pragma unroll
    for (int i = 0; i < 4; i++) {
        int x = 4 * q + i;
        xw4[r * 64 + SWZ(x)] = make_uint4(h[i][0], h[i][1], h[i][2], h[i][3]);
    }
}

// gather one (tap, px) over 8 channels: 4 LDS.128 corners, fp32 bilinear
__device__ __forceinline__ void gather_unit(const uint4* xw4, const float* xcb,
                                            uint32_t* bD, const int* sMI,
                                            const float4* sMW, int idx, int lo) {
    const int px = idx & 127, tap = idx >> 7;
    int mi = sMI[tap * 128 + px];
    float4 mw = sMW[tap * 128 + px];
    int cy0 = mi & 63, cy1 = (mi >> 6) & 63;
    int cx0 = (mi >> 12) & 63, cx1 = (mi >> 18) & 63;
    int wr0 = cy0 - lo, wr1 = cy1 - lo;
    bool in0 = (unsigned)wr0 < (unsigned)XROWS;
    bool in1 = (unsigned)wr1 < (unsigned)XROWS;
    uint32_t* bRow = bD + px;
    if (in0 && in1) {
        uint32_t c00[4], c01[4], c10[4], c11[4];
        *(uint4*)c00 = xw4[wr0 * 64 + SWZ(cx0)];
        *(uint4*)c01 = xw4[wr0 * 64 + SWZ(cx1)];
        *(uint4*)c10 = xw4[wr1 * 64 + SWZ(cx0)];
        *(uint4*)c11 = xw4[wr1 * 64 + SWZ(cx1)];
        #pragma unroll
        for (int jj = 0; jj < 4; jj++) {
            float2 f00 = __half22float2(*(__half2*)&c00[jj]);
            float2 f01 = __half22float2(*(__half2*)&c01[jj]);
            float2 f10 = __half22float2(*(__half2*)&c10[jj]);
            float2 f11 = __half22float2(*(__half2*)&c11[jj]);
            float vx = mw.x * f00.x;
            vx = fmaf(mw.y, f01.x, vx);
            vx = fmaf(mw.z, f10.x, vx);
            vx = fmaf(mw.w, f11.x, vx);
            float vy = mw.x * f00.y;
            vy = fmaf(mw.y, f01.y, vy);
            vy = fmaf(mw.z, f10.y, vy);
            vy = fmaf(mw.w, f11.y, vy);
            bRow[(tap * 4 + jj) * BST2] = h2u(__floats2half2_rn(vx, vy));
        }
    } else {  // rare: a sampled row falls outside the staged window
        #pragma unroll
        for (int jj = 0; jj < 4; jj++) {
            float vv[2];
            #pragma unroll
            for (int h = 0; h < 2; h++) {
                int ch = 2 * jj + h;
                const float* xp = xcb + ch * 4096;
                float v = mw.x * xp[cy0 * 64 + cx0];
                v = fmaf(mw.y, xp[cy0 * 64 + cx1], v);
                v = fmaf(mw.z, xp[cy1 * 64 + cx0], v);
                vv[h] = fmaf(mw.w, xp[cy1 * 64 + cx1], v);
            }
            bRow[(tap * 4 + jj) * BST2] = h2u(__floats2half2_rn(vv[0], vv[1]));
        }
    }
}

__global__ __launch_bounds__(THREADS, 2)
void deform_conv_cp(const float* __restrict__ x,
                    const float* __restrict__ offs,
                    float* __restrict__ out) {
    extern __shared__ char smem[];
    int*      sMI = (int*)(smem + OFF_MI);
    float4*   sMW = (float4*)(smem + OFF_MW);
    uint4*    sX4 = (uint4*)(smem + OFF_X);
    uint32_t* sBu = (uint32_t*)(smem + OFF_B);

    const int t = threadIdx.x, lane = t & 31, warp = t >> 5;
    const int b = blockIdx.x >> 5, ho2 = blockIdx.x & 31;
    const int lo = min(max(2 * ho2 - 5, 0), 64 - XROWS);
    const float* xg = x + b * 524288;

    // ---- tap metadata: 9 taps x 2 rows x 64 px ----
    const float* ob = offs + b * 18 * 4096;
    for (int i = t; i < 1152; i += THREADS) {
        int k = i >> 7, rp = i & 127, r = rp >> 6, p = rp & 63;
        int ho = 2 * ho2 + r;
        float dy = ob[(2 * k) * 4096 + ho * 64 + p];
        float dx = ob[(2 * k + 1) * 4096 + ho * 64 + p];
        float py = (float)(ho - 1 + k / 3) + dy;
        float px = (float)(p  - 1 + k % 3) + dx;
        float fy = floorf(py), fx = floorf(px);
        int y0 = (int)fy, x0 = (int)fx;
        float wy = py - fy, wx = px - fx;
        float wy1 = 1.f - wy, wx1 = 1.f - wx;
        float w00 = wy1 * wx1, w01 = wy1 * wx, w10 = wy * wx1, w11 = wy * wx;
        bool vy0 = (unsigned)y0       < 64u, vy1 = (unsigned)(y0 + 1) < 64u;
        bool vx0 = (unsigned)x0       < 64u, vx1 = (unsigned)(x0 + 1) < 64u;
        if (!(vy0 && vx0)) w00 = 0.f;
        if (!(vy0 && vx1)) w01 = 0.f;
        if (!(vy1 && vx0)) w10 = 0.f;
        if (!(vy1 && vx1)) w11 = 0.f;
        int cy0 = min(max(y0, 0), 63), cy1 = min(max(y0 + 1, 0), 63);
        int cx0 = min(max(x0, 0), 63), cx1 = min(max(x0 + 1, 0), 63);
        sMI[i] = cy0 | (cy1 << 6) | (cx0 << 12) | (cx1 << 18);
        sMW[i] = make_float4(w00, w01, w10, w11);
    }

    // ---- prologue: stage windows 0 and 1 (416 units) ----
    #pragma unroll
    for (int j = 0; j < 2; j++) {
        int idx = j * THREADS + t;
        if (idx < 416) {
            int w = idx >= 208;
            stage_unit(sX4 + w * XWIN4, xg + w * 8 * 4096, idx - w * 208, lo);
        }
    }
    __syncthreads();

    const int g = lane >> 2, tq = lane & 3;
    const int warpM = warp >> 1, warpN = warp & 1;
    float acc[2][8][4];
    #pragma unroll
    for (int m = 0; m < 2; m++)
        #pragma unroll
        for (int n = 0; n < 8; n++)
            #pragma unroll
            for (int c = 0; c < 4; c++) acc[m][n][c] = 0.f;

    // gather step 0 (all warps, 1152 units / 256 threads)
    #pragma unroll
    for (int u = 0; u < 5; u++) {
        int idx = u * THREADS + t;
        if (idx < 1152) gather_unit(sX4, xg, sBu, sMI, sMW, idx, lo);
    }

    // ---- main pipeline: 16 steps, one cg8 each ----
    for (int s = 0; s < NSTEP; s++) {
        __syncthreads();   // B(s) + X window s+1 ready

        // ---- MMA step s: 4 x k16 (tap pairs) + 1 x k8 (tap 8) ----
        {
            const uint32_t* bB = sBu + (s & 1) * BBUF + warpN * 64 + g;
            const uint32_t* aBase = g_wtF + ((s * 9) * 128 + warpM * 32) * 4 + lane;
            #pragma unroll
            for (int j = 0; j < 4; j++) {
                const uint32_t* ap  = aBase + (2 * j) * 512;
                const uint32_t* ap2 = ap + 512;
                uint32_t a00 = __ldg(ap),        a01 = __ldg(ap + 32);
                uint32_t a02 = __ldg(ap2),       a03 = __ldg(ap2 + 32);
                uint32_t a10 = __ldg(ap + 64),   a11 = __ldg(ap + 96);
                uint32_t a12 = __ldg(ap2 + 64),  a13 = __ldg(ap2 + 96);
                const uint32_t* b0p = bB + (8 * j + tq) * BST2;
                const uint32_t* b1p = bB + (8 * j + 4 + tq) * BST2;
                #pragma unroll
                for (int nt = 0; nt < 8; nt++) {
                    uint32_t b0 = b0p[nt * 8];
                    uint32_t b1 = b1p[nt * 8];
                    mma_k16(acc[0][nt], a00, a01, a02, a03, b0, b1);
                    mma_k16(acc[1][nt], a10, a11, a12, a13, b0, b1);
                }
            }
            {   // tap 8 tail (k8)
                const uint32_t* ap = aBase + 8 * 512;
                uint32_t a00 = __ldg(ap),      a01 = __ldg(ap + 32);
                uint32_t a10 = __ldg(ap + 64), a11 = __ldg(ap + 96);
                const uint32_t* bU = bB + (32 + tq) * BST2;
                #pragma unroll
                for (int nt = 0; nt < 8; nt++) {
                    uint32_t b0 = bU[nt * 8];
                    mma_k8(acc[0][nt], a00, a01, b0);
                    mma_k8(acc[1][nt], a10, a11, b0);
                }
            }
        }

        if (s == NSTEP - 1) break;

        // ---- all warps: gather step s+1 from window s+1 ----
        {
            const uint4* xw = sX4 + ((s + 1) & 1) * XWIN4;
            const float* xcb = xg + (s + 1) * 8 * 4096;
            uint32_t* bD = sBu + ((s + 1) & 1) * BBUF;
            #pragma unroll
            for (int u = 0; u < 5; u++) {
                int idx = u * THREADS + t;
                if (idx < 1152) gather_unit(xw, xcb, bD, sMI, sMW, idx, lo);
            }
        }
        // ---- all warps: stage window s+2 into buffer s&1 (window s dead) ----
        if (s + 2 < NSTEP && t < 208)
            stage_unit(sX4 + (s & 1) * XWIN4, xg + (s + 2) * 8 * 4096, t, lo);
    }

    // ---- epilogue: D[m=cout][n] -> out row 2*ho2+warpN ----
    float* o = out + b * 524288 + (2 * ho2 + warpN) * 64;
    #pragma unroll
    for (int mt = 0; mt < 2; mt++) {
        int row0 = warpM * 32 + mt * 16 + g;
        #pragma unroll
        for (int nt = 0; nt < 8; nt++) {
            int p = nt * 8 + 2 * tq;
            *(float2*)(o + row0 * 4096 + p) =
                make_float2(acc[mt][nt][0], acc[mt][nt][1]);
            *(float2*)(o + (row0 + 8) * 4096 + p) =
                make_float2(acc[mt][nt][2], acc[mt][nt][3]);
        }
    }
}

extern "C" void kernel_launch(void* const* d_in, const int* in_sizes, int n_in,
                              void* d_out, int out_size) {
    const float* x    = (const float*)d_in[0];
    const float* offs = (const float*)d_in[1];
    const float* wgt  = (const float*)d_in[2];
    wt_permute<<<(NSTEP * 9 * 128 * 4 + 255) / 256, 256>>>(wgt);
    cudaFuncSetAttribute(deform_conv_cp,
                         cudaFuncAttributeMaxDynamicSharedMemorySize, SMEM_TOTAL);
    deform_conv_cp<<<256, THREADS, SMEM_TOTAL>>>(x, offs, (float*)d_out);
}

// round 12
// speedup vs baseline: 1.9783x; 1.0042x over previous
#include <cuda_runtime.h>
#include <cuda_fp16.h>
#include <cstdint>

// Deformable conv2d B=8, Cin=Cout=128, H=W=64, 3x3 s1 p1 DG=1.
// f16 HMMA m16n8k16 (fp32 accum). Channel-packed fp16 X window (LDS.128 = 8ch).
// B tile [px][k-contig] fed to MMA via ldmatrix.x4; A via lane-contig LDG.128.
// One CTA per (b, ho-pair): 256 CTAs, N=128, 16 steps of K=72.

#define THREADS 256
static constexpr int KTOT = 1152;
static constexpr int NSTEP = 16;            // one cg8 per step, K=72

static constexpr int XROWS = 13;
static constexpr int XWIN4 = XROWS * 64;    // uint4 per window buffer = 832
static constexpr int BSTR  = 36;            // B row stride in u32 (72 half, 144B)
static constexpr int BBUF  = 128 * BSTR;    // 4608 u32 per buffer
static constexpr int BBUFB = BBUF * 4;      // 18432 B

// smem layout (bytes)
static constexpr int OFF_MI = 0;            // int[1152]      4608
static constexpr int OFF_MW = 4608;         // float4[1152]  18432
static constexpr int OFF_X  = 23040;        // 2 x 13312 =   26624
static constexpr int OFF_B  = 49664;        // 2 x 18432 =   36864
static constexpr int SMEM_TOTAL = 86528;

#define SWZ(x) ((x) ^ (((x) >> 3) & 7))

// A weights, lane-contiguous uint4: [step][tapgrp(2)][row(128)][tq(4)] -> taps 4tg..4tg+3
__device__ uint4    g_wtA[NSTEP * 2 * 128 * 4];
// tap-8 tail: [step][row][tq]
__device__ uint32_t g_wtA8[NSTEP * 128 * 4];

__device__ __forceinline__ void mma_k16(float* d, uint32_t a0, uint32_t a1,
                                        uint32_t a2, uint32_t a3,
                                        uint32_t b0, uint32_t b1) {
    asm volatile(
        "mma.sync.aligned.m16n8k16.row.col.f32.f16.f16.f32 "
        "{%0,%1,%2,%3}, {%4,%5,%6,%7}, {%8,%9}, {%0,%1,%2,%3};"
        : "+f"(d[0]), "+f"(d[1]), "+f"(d[2]), "+f"(d[3])
        : "r"(a0), "r"(a1), "r"(a2), "r"(a3), "r"(b0), "r"(b1));
}
__device__ __forceinline__ void mma_k8(float* d, uint32_t a0, uint32_t a1,
                                       uint32_t b0) {
    asm volatile(
        "mma.sync.aligned.m16n8k8.row.col.f32.f16.f16.f32 "
        "{%0,%1,%2,%3}, {%4,%5}, {%6}, {%0,%1,%2,%3};"
        : "+f"(d[0]), "+f"(d[1]), "+f"(d[2]), "+f"(d[3])
        : "r"(a0), "r"(a1), "r"(b0));
}
__device__ __forceinline__ void ldsm4(uint32_t* r, uint32_t addr) {
    asm volatile(
        "ldmatrix.sync.aligned.m8n8.x4.shared.b16 {%0,%1,%2,%3}, [%4];"
        : "=r"(r[0]), "=r"(r[1]), "=r"(r[2]), "=r"(r[3]) : "r"(addr));
}
__device__ __forceinline__ uint32_t h2u(__half2 h) { return *(uint32_t*)&h; }

__global__ void wt_permute(const float* __restrict__ w) {
    int idx = blockIdx.x * 256 + threadIdx.x;
    if (idx >= NSTEP * 128 * 4) return;
    int tq = idx & 3, row = (idx >> 2) & 127, s = idx >> 9;
    int ch0 = s * 8 + 2 * tq;
    const float* w0 = w + row * KTOT + ch0 * 9;
    const float* w1 = w0 + 9;
    #pragma unroll
    for (int tg = 0; tg < 2; tg++) {
        uint4 v;
        v.x = h2u(__floats2half2_rn(w0[4 * tg + 0], w1[4 * tg + 0]));
        v.y = h2u(__floats2half2_rn(w0[4 * tg + 1], w1[4 * tg + 1]));
        v.z = h2u(__floats2half2_rn(w0[4 * tg + 2], w1[4 * tg + 2]));
        v.w = h2u(__floats2half2_rn(w0[4 * tg + 3], w1[4 * tg + 3]));
        g_wtA[((s * 2 + tg) * 128 + row) * 4 + tq] = v;
    }
    g_wtA8[idx] = h2u(__floats2half2_rn(w0[8], w1[8]));
}

// stage one (row, x-quad) of a window: 8 coalesced LDG.128 + 4 swizzled STS.128
__device__ __forceinline__ void stage_unit(uint4* xw4, const float* xcb,
                                           int u, int lo) {
    int r = u >> 4, q = u & 15;
    const float* src = xcb + (lo + r) * 64 + 4 * q;
    uint32_t h[4][4];
    #pragma unroll
    for (int p = 0; p < 4; p++) {
        float4 a = *(const float4*)(src + (2 * p) * 4096);
        float4 b = *(const float4*)(src + (2 * p + 1) * 4096);
        h[0][p] = h2u(__floats2half2_rn(a.x, b.x));
        h[1][p] = h2u(__floats2half2_rn(a.y, b.y));
        h[2][p] = h2u(__floats2half2_rn(a.z, b.z));
        h[3][p] = h2u(__floats2half2_rn(a.w, b.w));
    }
    #pragma unroll
    for (int i = 0; i < 4; i++) {
        int x = 4 * q + i;
        xw4[r * 64 + SWZ(x)] = make_uint4(h[i][0], h[i][1], h[i][2], h[i][3]);
    }
}

// gather one (tap, px) over 8 channels: 4 LDS.128 corners -> 1 STS.128
__device__ __forceinline__ void gather_unit(const uint4* xw4, const float* xcb,
                                            uint32_t* bD, const int* sMI,
                                            const float4* sMW, int idx, int lo) {
    const int px = idx & 127, tap = idx >> 7;
    int mi = sMI[tap * 128 + px];
    float4 mw = sMW[tap * 128 + px];
    int cy0 = mi & 63, cy1 = (mi >> 6) & 63;
    int cx0 = (mi >> 12) & 63, cx1 = (mi >> 18) & 63;
    int wr0 = cy0 - lo, wr1 = cy1 - lo;
    bool in0 = (unsigned)wr0 < (unsigned)XROWS;
    bool in1 = (unsigned)wr1 < (unsigned)XROWS;
    uint32_t ov[4];
    if (in0 && in1) {
        uint32_t c00[4], c01[4], c10[4], c11[4];
        *(uint4*)c00 = xw4[wr0 * 64 + SWZ(cx0)];
        *(uint4*)c01 = xw4[wr0 * 64 + SWZ(cx1)];
        *(uint4*)c10 = xw4[wr1 * 64 + SWZ(cx0)];
        *(uint4*)c11 = xw4[wr1 * 64 + SWZ(cx1)];
        #pragma unroll
        for (int jj = 0; jj < 4; jj++) {
            float2 f00 = __half22float2(*(__half2*)&c00[jj]);
            float2 f01 = __half22float2(*(__half2*)&c01[jj]);
            float2 f10 = __half22float2(*(__half2*)&c10[jj]);
            float2 f11 = __half22float2(*(__half2*)&c11[jj]);
            float vx = mw.x * f00.x;
            vx = fmaf(mw.y, f01.x, vx);
            vx = fmaf(mw.z, f10.x, vx);
            vx = fmaf(mw.w, f11.x, vx);
            float vy = mw.x * f00.y;
            vy = fmaf(mw.y, f01.y, vy);
            vy = fmaf(mw.z, f10.y, vy);
            vy = fmaf(mw.w, f11.y, vy);
            ov[jj] = h2u(__floats2half2_rn(vx, vy));
        }
    } else {  // rare: a sampled row falls outside the staged window
        #pragma unroll
        for (int jj = 0; jj < 4; jj++) {
            float vv[2];
            #pragma unroll
            for (int h = 0; h < 2; h++) {
                int ch = 2 * jj + h;
                const float* xp = xcb + ch * 4096;
                float v = mw.x * xp[cy0 * 64 + cx0];
                v = fmaf(mw.y, xp[cy0 * 64 + cx1], v);
                v = fmaf(mw.z, xp[cy1 * 64 + cx0], v);
                vv[h] = fmaf(mw.w, xp[cy1 * 64 + cx1], v);
            }
            ov[jj] = h2u(__floats2half2_rn(vv[0], vv[1]));
        }
    }
    *(uint4*)(bD + px * BSTR + tap * 4) = make_uint4(ov[0], ov[1], ov[2], ov[3]);
}

__global__ __launch_bounds__(THREADS, 2)
void deform_conv_lm(const float* __restrict__ x,
                    const float* __restrict__ offs,
                    float* __restrict__ out) {
    extern __shared__ char smem[];
    int*      sMI = (int*)(smem + OFF_MI);
    float4*   sMW = (float4*)(smem + OFF_MW);
    uint4*    sX4 = (uint4*)(smem + OFF_X);
    uint32_t* sBu = (uint32_t*)(smem + OFF_B);

    const int t = threadIdx.x, lane = t & 31, warp = t >> 5;
    const int b = blockIdx.x >> 5, ho2 = blockIdx.x & 31;
    const int lo = min(max(2 * ho2 - 5, 0), 64 - XROWS);
    const float* xg = x + b * 524288;

    // ---- tap metadata: 9 taps x 2 rows x 64 px ----
    const float* ob = offs + b * 18 * 4096;
    for (int i = t; i < 1152; i += THREADS) {
        int k = i >> 7, rp = i & 127, r = rp >> 6, p = rp & 63;
        int ho = 2 * ho2 + r;
        float dy = ob[(2 * k) * 4096 + ho * 64 + p];
        float dx = ob[(2 * k + 1) * 4096 + ho * 64 + p];
        float py = (float)(ho - 1 + k / 3) + dy;
        float px = (float)(p  - 1 + k % 3) + dx;
        float fy = floorf(py), fx = floorf(px);
        int y0 = (int)fy, x0 = (int)fx;
        float wy = py - fy, wx = px - fx;
        float wy1 = 1.f - wy, wx1 = 1.f - wx;
        float w00 = wy1 * wx1, w01 = wy1 * wx, w10 = wy * wx1, w11 = wy * wx;
        bool vy0 = (unsigned)y0       < 64u, vy1 = (unsigned)(y0 + 1) < 64u;
        bool vx0 = (unsigned)x0       < 64u, vx1 = (unsigned)(x0 + 1) < 64u;
        if (!(vy0 && vx0)) w00 = 0.f;
        if (!(vy0 && vx1)) w01 = 0.f;
        if (!(vy1 && vx0)) w10 = 0.f;
        if (!(vy1 && vx1)) w11 = 0.f;
        int cy0 = min(max(y0, 0), 63), cy1 = min(max(y0 + 1, 0), 63);
        int cx0 = min(max(x0, 0), 63), cx1 = min(max(x0 + 1, 0), 63);
        sMI[i] = cy0 | (cy1 << 6) | (cx0 << 12) | (cx1 << 18);
        sMW[i] = make_float4(w00, w01, w10, w11);
    }

    // ---- prologue: stage windows 0 and 1 (416 units) ----
    #pragma unroll
    for (int j = 0; j < 2; j++) {
        int idx = j * THREADS + t;
        if (idx < 416) {
            int w = idx >= 208;
            stage_unit(sX4 + w * XWIN4, xg + w * 8 * 4096, idx - w * 208, lo);
        }
    }
    __syncthreads();

    const int g = lane >> 2, tq = lane & 3;
    const int warpM = warp >> 1, warpN = warp & 1;
    float acc[2][8][4];
    #pragma unroll
    for (int m = 0; m < 2; m++)
        #pragma unroll
        for (int n = 0; n < 8; n++)
            #pragma unroll
            for (int c = 0; c < 4; c++) acc[m][n][c] = 0.f;

    // ldmatrix per-thread address offsets (bytes within a B buffer)
    const uint32_t sBuAddr = (uint32_t)__cvta_generic_to_shared(sBu);
    const int rr = lane & 7;
    const uint32_t bOffJ = (uint32_t)((warpN * 64 + ((lane >> 4) & 1) * 8 + rr) * 144
                                      + ((lane >> 3) & 1) * 16);
    const uint32_t bOffT = (uint32_t)((warpN * 64 + ((lane >> 3) & 3) * 8 + rr) * 144 + 128);

    // gather step 0 (all warps, 1152 units / 256 threads)
    #pragma unroll
    for (int u = 0; u < 5; u++) {
        int idx = u * THREADS + t;
        if (idx < 1152) gather_unit(sX4, xg, sBu, sMI, sMW, idx, lo);
    }

    // ---- main pipeline: 16 steps, one cg8 each ----
    for (int s = 0; s < NSTEP; s++) {
        __syncthreads();   // B(s) + X window s+1 ready

        // ---- MMA step s ----
        {
            const uint32_t bBase = sBuAddr + (s & 1) * BBUFB;
            const int aRow = warpM * 32 + g;
            #pragma unroll
            for (int half = 0; half < 2; half++) {
                uint4 Ar[4];
                #pragma unroll
                for (int r4 = 0; r4 < 4; r4++)
                    Ar[r4] = __ldg(&g_wtA[((s * 2 + half) * 128 + aRow + r4 * 8) * 4 + tq]);
                const uint32_t* Au = (const uint32_t*)Ar;
                #pragma unroll
                for (int jj = 0; jj < 2; jj++) {
                    const int j = 2 * half + jj;
                    uint32_t bb[16];
                    #pragma unroll
                    for (int i = 0; i < 4; i++)
                        ldsm4(bb + 4 * i, bBase + bOffJ + j * 32 + i * 2304);
                    uint32_t a00 = Au[0 * 4 + 2 * jj], a02 = Au[0 * 4 + 2 * jj + 1];
                    uint32_t a01 = Au[1 * 4 + 2 * jj], a03 = Au[1 * 4 + 2 * jj + 1];
                    uint32_t a10 = Au[2 * 4 + 2 * jj], a12 = Au[2 * 4 + 2 * jj + 1];
                    uint32_t a11 = Au[3 * 4 + 2 * jj], a13 = Au[3 * 4 + 2 * jj + 1];
                    #pragma unroll
                    for (int nt = 0; nt < 8; nt++) {
                        uint32_t b0 = bb[4 * (nt >> 1) + (nt & 1) * 2];
                        uint32_t b1 = bb[4 * (nt >> 1) + (nt & 1) * 2 + 1];
                        mma_k16(acc[0][nt], a00, a01, a02, a03, b0, b1);
                        mma_k16(acc[1][nt], a10, a11, a12, a13, b0, b1);
                    }
                }
            }
            {   // tap-8 tail (k8)
                uint32_t A8[4];
                #pragma unroll
                for (int r4 = 0; r4 < 4; r4++)
                    A8[r4] = __ldg(&g_wtA8[(s * 128 + aRow + r4 * 8) * 4 + tq]);
                uint32_t bb[8];
                #pragma unroll
                for (int i2 = 0; i2 < 2; i2++)
                    ldsm4(bb + 4 * i2, bBase + bOffT + i2 * 4608);
                #pragma unroll
                for (int nt = 0; nt < 8; nt++) {
                    mma_k8(acc[0][nt], A8[0], A8[1], bb[nt]);
                    mma_k8(acc[1][nt], A8[2], A8[3], bb[nt]);
                }
            }
        }

        if (s == NSTEP - 1) break;

        // ---- all warps: gather step s+1 from window s+1 ----
        {
            const uint4* xw = sX4 + ((s + 1) & 1) * XWIN4;
            const float* xcb = xg + (s + 1) * 8 * 4096;
            uint32_t* bD = sBu + ((s + 1) & 1) * BBUF;
            #pragma unroll
            for (int u = 0; u < 5; u++) {
                int idx = u * THREADS + t;
                if (idx < 1152) gather_unit(xw, xcb, bD, sMI, sMW, idx, lo);
            }
        }
        // ---- all warps: stage window s+2 into buffer s&1 (window s dead) ----
        if (s + 2 < NSTEP && t < 208)
            stage_unit(sX4 + (s & 1) * XWIN4, xg + (s + 2) * 8 * 4096, t, lo);
    }

    // ---- epilogue: D[m=cout][n] -> out row 2*ho2+warpN ----
    float* o = out + b * 524288 + (2 * ho2 + warpN) * 64;
    #pragma unroll
    for (int mt = 0; mt < 2; mt++) {
        int row0 = warpM * 32 + mt * 16 + g;
        #pragma unroll
        for (int nt = 0; nt < 8; nt++) {
            int p = nt * 8 + 2 * tq;
            *(float2*)(o + row0 * 4096 + p) =
                make_float2(acc[mt][nt][0], acc[mt][nt][1]);
            *(float2*)(o + (row0 + 8) * 4096 + p) =
                make_float2(acc[mt][nt][2], acc[mt][nt][3]);
        }
    }
}

extern "C" void kernel_launch(void* const* d_in, const int* in_sizes, int n_in,
                              void* d_out, int out_size) {
    const float* x    = (const float*)d_in[0];
    const float* offs = (const float*)d_in[1];
    const float* wgt  = (const float*)d_in[2];
    wt_permute<<<(NSTEP * 128 * 4 + 255) / 256, 256>>>(wgt);
    cudaFuncSetAttribute(deform_conv_lm,
                         cudaFuncAttributeMaxDynamicSharedMemorySize, SMEM_TOTAL);
    deform_conv_lm<<<256, THREADS, SMEM_TOTAL>>>(x, offs, (float*)d_out);
}